// round 1
// baseline (speedup 1.0000x reference)
#include <cuda_runtime.h>
#include <cstdint>

// EarthAttention2D fused kernel: one CTA per window.
// Phases: load x -> QKV GEMM (f32x2, smem-staged W) -> per-head attention
// (padded q/k scratch, smem bias-table slice, warp softmax) -> out projection.

#define NTOK   72
#define DIMX   192
#define NH     6
#define HD     32
#define TOWC   31
#define NWC    30
#define BLK    384
#define NSQ    5184     // 72*72
#define TBLROWS 828

// shared memory float offsets
#define OFF_Q   0
#define OFF_K   13824
#define OFF_V   27648
#define OFF_SCR 41472
// scratch sub-offsets (attention phase; QKV phase uses [0,13824) as x)
#define SCR_S   0
#define SCR_QP  5184
#define SCR_KP  7632
#define SCR_TBL 10080
#define SCR_RS  15048
#define SMEM_FLOATS (41472 + 15120)
#define SMEM_BYTES  (SMEM_FLOATS * 4)   // 226368 <= 232448

typedef unsigned long long u64;

__device__ __forceinline__ u64 fma2(u64 a, u64 b, u64 c) {
    u64 d;
    asm("fma.rn.f32x2 %0, %1, %2, %3;" : "=l"(d) : "l"(a), "l"(b), "l"(c));
    return d;
}
__device__ __forceinline__ u64 dup2(float x) {
    u64 d; unsigned u = __float_as_uint(x);
    asm("mov.b64 %0, {%1, %1};" : "=l"(d) : "r"(u));
    return d;
}
__device__ __forceinline__ float2 un2(u64 a) {
    float2 f;
    asm("mov.b64 {%0, %1}, %2;" : "=f"(f.x), "=f"(f.y) : "l"(a));
    return f;
}

// C[72][192] = in_sm[72][192] @ Wg[192-rows x 192-cols slice] (+ bias) * scale
// Wg points at the column slice already; row stride = wstride.
// stage: smem [32][192] staging buffer for W tiles.
__device__ __forceinline__ void gemm192(
    int tid,
    const float* __restrict__ in_sm,
    const float* __restrict__ Wg, int wstride,
    float* stage,
    const float* __restrict__ bvec,
    float scale,
    float* out_sm,          // if non-null, write here
    float* out_g)           // else here (global, row stride 192)
{
    const int tx = tid & 31, ty = tid >> 5;
    const int r0 = ty * 6, c0 = tx * 6;
    u64 acc[6][3];
#pragma unroll
    for (int a = 0; a < 6; a++)
#pragma unroll
        for (int b = 0; b < 3; b++) acc[a][b] = 0ull;

    for (int kt = 0; kt < 6; kt++) {
        const int k0 = kt * 32;
        // stage W tile [32][192], coalesced float4
#pragma unroll
        for (int it = 0; it < 4; it++) {
            int l = tid + it * BLK;
            int row = l / 48, c4 = l % 48;
            float4 v = *(const float4*)(Wg + (size_t)(k0 + row) * wstride + c4 * 4);
            *(float4*)(stage + row * 192 + c4 * 4) = v;
        }
        __syncthreads();
#pragma unroll
        for (int kk4 = 0; kk4 < 8; kk4++) {
            float4 xv[6];
#pragma unroll
            for (int rr = 0; rr < 6; rr++)
                xv[rr] = *(const float4*)(in_sm + (r0 + rr) * 192 + k0 + kk4 * 4);
#pragma unroll
            for (int u = 0; u < 4; u++) {
                const float* wrow = stage + (kk4 * 4 + u) * 192 + c0;
                u64 w0 = *(const u64*)(wrow);
                u64 w1 = *(const u64*)(wrow + 2);
                u64 w2 = *(const u64*)(wrow + 4);
#pragma unroll
                for (int rr = 0; rr < 6; rr++) {
                    float xs = (u == 0) ? xv[rr].x : (u == 1) ? xv[rr].y
                             : (u == 2) ? xv[rr].z : xv[rr].w;
                    u64 xd = dup2(xs);
                    acc[rr][0] = fma2(xd, w0, acc[rr][0]);
                    acc[rr][1] = fma2(xd, w1, acc[rr][1]);
                    acc[rr][2] = fma2(xd, w2, acc[rr][2]);
                }
            }
        }
        __syncthreads();   // all reads of stage done before next overwrite / epilogue
    }
#pragma unroll
    for (int cc = 0; cc < 3; cc++) {
        float bx = bvec[c0 + cc * 2], by = bvec[c0 + cc * 2 + 1];
#pragma unroll
        for (int rr = 0; rr < 6; rr++) {
            float2 a = un2(acc[rr][cc]);
            a.x = (a.x + bx) * scale;
            a.y = (a.y + by) * scale;
            if (out_sm) *(float2*)(out_sm + (r0 + rr) * 192 + c0 + cc * 2) = a;
            else        *(float2*)(out_g + (size_t)(r0 + rr) * 192 + c0 + cc * 2) = a;
        }
    }
}

__global__ __launch_bounds__(BLK, 1)
void earth_attn_kernel(
    const float* __restrict__ x,
    const float* __restrict__ mask,
    const float* __restrict__ wqkv,
    const float* __restrict__ bqkv,
    const float* __restrict__ wout,
    const float* __restrict__ bout,
    const float* __restrict__ tbl,
    float* __restrict__ out)
{
    extern __shared__ float sm[];
    const int c   = blockIdx.x;
    const int tid = threadIdx.x;

    float* qs  = sm + OFF_Q;
    float* ks  = sm + OFF_K;
    float* vs  = sm + OFF_V;
    float* scr = sm + OFF_SCR;

    const int t_idx = c % TOWC;
    const int s_sh  = c / TOWC;
    const int m_idx = c % NWC;

    // ---- Phase 1: load x tile into scratch ----
    {
        const float4* xg = (const float4*)(x + (size_t)c * (NTOK * DIMX));
        float4* xd = (float4*)scr;
#pragma unroll
        for (int i = tid; i < NTOK * DIMX / 4; i += BLK) xd[i] = xg[i];
    }
    __syncthreads();

    // ---- Phase 2: QKV GEMM. Order V, K, Q (Q region is the staging buffer). ----
    const float scale = 0.1767766952966369f;  // 32^-0.5
    gemm192(tid, scr, wqkv + 384, 576, qs, bqkv + 384, 1.0f,   vs, nullptr);
    gemm192(tid, scr, wqkv + 192, 576, qs, bqkv + 192, 1.0f,   ks, nullptr);
    gemm192(tid, scr, wqkv + 0,   576, qs, bqkv + 0,   scale,  qs, nullptr);

    // ---- Phase 3: load bias-table slice for this window's latitude t ----
    float* Sb = scr + SCR_S;
    float* qp = scr + SCR_QP;
    float* kp = scr + SCR_KP;
    float* tb = scr + SCR_TBL;
    float* rs = scr + SCR_RS;
    for (int i2 = tid; i2 < TBLROWS * NH; i2 += BLK) {
        int r = i2 / NH, hh = i2 - r * NH;
        tb[i2] = tbl[(r * TOWC + t_idx) * NH + hh];
    }
    __syncthreads();   // q epilogue + table slice visible

    const int wid = tid >> 5, lane = tid & 31;

    // ---- Phase 4: per-head attention ----
    for (int h = 0; h < NH; h++) {
        // copy q_h, k_h into stride-34 padded scratch (bank-conflict-free dots)
        for (int i2 = tid; i2 < NTOK * HD; i2 += BLK) {
            int r = i2 >> 5, d = i2 & 31;
            qp[r * 34 + d] = qs[r * 192 + h * 32 + d];
            kp[r * 34 + d] = ks[r * 192 + h * 32 + d];
        }
        __syncthreads();

        // S = q_h k_h^T + earth_bias + mask
        {
            int p = (tid * 60 + s_sh) % NSQ;
            for (int e = tid; e < NSQ; e += BLK) {
                int i = e / NTOK, j = e - i * NTOK;
                const u64* qrow = (const u64*)(qp + i * 34);
                const u64* krow = (const u64*)(kp + j * 34);
                u64 a0 = 0ull, a1 = 0ull;
#pragma unroll
                for (int d2 = 0; d2 < 16; d2 += 2) {
                    a0 = fma2(qrow[d2],     krow[d2],     a0);
                    a1 = fma2(qrow[d2 + 1], krow[d2 + 1], a1);
                }
                float2 f0 = un2(a0), f1 = un2(a1);
                float dot = (f0.x + f0.y) + (f1.x + f1.y);
                int n2 = p / NTOK, m2 = p - n2 * NTOK;
                int posv = (n2 / 12 + 6 * (m2 / 12)) * 23 + (n2 % 12) - (m2 % 12) + 11;
                float bias = tb[posv * NH + h];
                float mv   = mask[(size_t)m_idx * NSQ + e];
                Sb[e] = dot + bias + mv;
                p += 2304; if (p >= NSQ) p -= NSQ;
            }
        }
        __syncthreads();

        // softmax: one warp per row (72 = 32 + 32 + 8)
        for (int rr = wid; rr < NTOK; rr += 12) {
            float v0 = Sb[rr * 72 + lane];
            float v1 = Sb[rr * 72 + lane + 32];
            float v2 = (lane < 8) ? Sb[rr * 72 + lane + 64] : -1e30f;
            float m = fmaxf(v0, fmaxf(v1, v2));
#pragma unroll
            for (int o = 16; o > 0; o >>= 1) m = fmaxf(m, __shfl_xor_sync(0xffffffffu, m, o));
            v0 = __expf(v0 - m);
            v1 = __expf(v1 - m);
            v2 = (lane < 8) ? __expf(v2 - m) : 0.0f;
            float sum = v0 + v1 + v2;
#pragma unroll
            for (int o = 16; o > 0; o >>= 1) sum += __shfl_xor_sync(0xffffffffu, sum, o);
            Sb[rr * 72 + lane]      = v0;
            Sb[rr * 72 + lane + 32] = v1;
            if (lane < 8) Sb[rr * 72 + lane + 64] = v2;
            if (lane == 0) rs[rr] = 1.0f / sum;
        }
        __syncthreads();

        // out_h = softmax(S) @ v_h  -> overwrite q_h slice
        for (int u = tid; u < NTOK * 16; u += BLK) {
            int i = u >> 4, d2 = (u & 15) * 2;
            const float* srow = Sb + i * 72;
            const float* vcol = vs + h * 32 + d2;
            u64 acc = 0ull;
#pragma unroll 8
            for (int j = 0; j < 72; j++)
                acc = fma2(dup2(srow[j]), *(const u64*)(vcol + j * 192), acc);
            float2 a = un2(acc);
            float rv = rs[i];
            a.x *= rv; a.y *= rv;
            *(float2*)(qs + i * 192 + h * 32 + d2) = a;
        }
        __syncthreads();
    }

    // ---- Phase 5: out projection, stream straight to global ----
    gemm192(tid, qs, wout, 192, ks, bout, 1.0f,
            nullptr, out + (size_t)c * (NTOK * DIMX));
}

extern "C" void kernel_launch(void* const* d_in, const int* in_sizes, int n_in,
                              void* d_out, int out_size)
{
    const float* x    = (const float*)d_in[0];
    const float* mask = (const float*)d_in[1];
    const float* wqkv = (const float*)d_in[2];
    const float* bqkv = (const float*)d_in[3];
    const float* wout = (const float*)d_in[4];
    const float* bout = (const float*)d_in[5];
    const float* tbl  = (const float*)d_in[6];
    float* out = (float*)d_out;

    int B_ = in_sizes[0] / (NTOK * DIMX);   // 1860

    cudaFuncSetAttribute(earth_attn_kernel,
                         cudaFuncAttributeMaxDynamicSharedMemorySize, SMEM_BYTES);
    earth_attn_kernel<<<B_, BLK, SMEM_BYTES>>>(x, mask, wqkv, bqkv, wout, bout, tbl, out);
}

// round 3
// speedup vs baseline: 1.2114x; 1.2114x over previous
#include <cuda_runtime.h>
#include <cstdint>

// EarthAttention2D fused kernel v2: one CTA per window.
// Register-tiled QK^T and AV, k written in per-head padded layout by the
// K-GEMM epilogue, head-invariant bias index precomputed once.

#define NTOK   72
#define DIMX   192
#define NH     6
#define HD     32
#define TOWC   31
#define NWC    30
#define BLK    384
#define NSQ    5184     // 72*72
#define TBLROWS 828
#define KPITCH 34
#define KH_HEAD (NTOK * KPITCH)      // 2448

// shared memory float offsets
#define OFF_Q   0                    // q / attn-out, 72x192 pitch 192 (13824)
#define OFF_KH  13824                // k per-head padded: 6 x 72 x 34 (14688)
#define OFF_V   28512                // v, 72x192 pitch 192 (13824)
#define OFF_R   42336                // union region (13824)
//   QKV phase:  R = x tile (13824)
//   attn phase: R = Sb(5184) | tb(4968) | rs(@10152) | pidx u16 (@10224, 2592f)
#define R_S     0
#define R_TB    5184
#define R_RS    10152
#define R_PIDX  10224
#define SMEM_FLOATS (OFF_R + 13824)  // 56160
#define SMEM_BYTES  (SMEM_FLOATS * 4)  // 224640

typedef unsigned long long u64;

__device__ __forceinline__ u64 fma2(u64 a, u64 b, u64 c) {
    u64 d;
    asm("fma.rn.f32x2 %0, %1, %2, %3;" : "=l"(d) : "l"(a), "l"(b), "l"(c));
    return d;
}
__device__ __forceinline__ u64 dup2(float x) {
    u64 d; unsigned u = __float_as_uint(x);
    asm("mov.b64 %0, {%1, %1};" : "=l"(d) : "r"(u));
    return d;
}
__device__ __forceinline__ float2 un2(u64 a) {
    float2 f;
    asm("mov.b64 {%0, %1}, %2;" : "=f"(f.x), "=f"(f.y) : "l"(a));
    return f;
}

// C[72][192] = in_sm[72][192] @ Wg(192x192 col slice, row stride wstride) + b.
// MODE 0: write smem pitch-192 (scaled). MODE 1: write per-head padded kh.
// MODE 2: write global pitch-192.
template<int MODE>
__device__ __forceinline__ void gemm192(
    int tid,
    const float* __restrict__ in_sm,
    const float* __restrict__ Wg, int wstride,
    float* stage,
    const float* __restrict__ bvec,
    float scale,
    float* outp)
{
    const int tx = tid & 31, ty = tid >> 5;
    const int r0 = ty * 6, c0 = tx * 6;
    u64 acc[6][3];
#pragma unroll
    for (int a = 0; a < 6; a++)
#pragma unroll
        for (int b = 0; b < 3; b++) acc[a][b] = 0ull;

    for (int kt = 0; kt < 6; kt++) {
        const int k0 = kt * 32;
#pragma unroll
        for (int it = 0; it < 4; it++) {
            int l = tid + it * BLK;
            int row = l / 48, c4 = l % 48;
            float4 v = *(const float4*)(Wg + (size_t)(k0 + row) * wstride + c4 * 4);
            *(float4*)(stage + row * 192 + c4 * 4) = v;
        }
        __syncthreads();
#pragma unroll
        for (int kk4 = 0; kk4 < 8; kk4++) {
            float4 xv[6];
#pragma unroll
            for (int rr = 0; rr < 6; rr++)
                xv[rr] = *(const float4*)(in_sm + (r0 + rr) * 192 + k0 + kk4 * 4);
#pragma unroll
            for (int u = 0; u < 4; u++) {
                const float* wrow = stage + (kk4 * 4 + u) * 192 + c0;
                u64 w0 = *(const u64*)(wrow);
                u64 w1 = *(const u64*)(wrow + 2);
                u64 w2 = *(const u64*)(wrow + 4);
#pragma unroll
                for (int rr = 0; rr < 6; rr++) {
                    float xs = (u == 0) ? xv[rr].x : (u == 1) ? xv[rr].y
                             : (u == 2) ? xv[rr].z : xv[rr].w;
                    u64 xd = dup2(xs);
                    acc[rr][0] = fma2(xd, w0, acc[rr][0]);
                    acc[rr][1] = fma2(xd, w1, acc[rr][1]);
                    acc[rr][2] = fma2(xd, w2, acc[rr][2]);
                }
            }
        }
        __syncthreads();
    }
#pragma unroll
    for (int cc = 0; cc < 3; cc++) {
        float bx = bvec[c0 + cc * 2], by = bvec[c0 + cc * 2 + 1];
#pragma unroll
        for (int rr = 0; rr < 6; rr++) {
            float2 a = un2(acc[rr][cc]);
            a.x = (a.x + bx) * scale;
            a.y = (a.y + by) * scale;
            int col = c0 + cc * 2;
            if (MODE == 0) {
                *(float2*)(outp + (r0 + rr) * 192 + col) = a;
            } else if (MODE == 1) {
                outp[(col >> 5) * KH_HEAD + (r0 + rr) * KPITCH + (col & 31)] = a.x;
                outp[((col + 1) >> 5) * KH_HEAD + (r0 + rr) * KPITCH + ((col + 1) & 31)] = a.y;
            } else {
                *(float2*)(outp + (size_t)(r0 + rr) * 192 + col) = a;
            }
        }
    }
}

__global__ __launch_bounds__(BLK, 1)
void earth_attn_kernel(
    const float* __restrict__ x,
    const float* __restrict__ mask,
    const float* __restrict__ wqkv,
    const float* __restrict__ bqkv,
    const float* __restrict__ wout,
    const float* __restrict__ bout,
    const float* __restrict__ tbl,
    float* __restrict__ out)
{
    extern __shared__ float sm[];
    const int c   = blockIdx.x;
    const int tid = threadIdx.x;

    float* qs = sm + OFF_Q;
    float* kh = sm + OFF_KH;
    float* vs = sm + OFF_V;
    float* R  = sm + OFF_R;

    const int t_idx = c % TOWC;
    const int s_sh  = c / TOWC;
    const int m_idx = c % NWC;
    const float* maskg = mask + (size_t)m_idx * NSQ;

    // ---- Phase 1: load x tile ----
    {
        const float4* xg = (const float4*)(x + (size_t)c * (NTOK * DIMX));
        float4* xd = (float4*)R;
#pragma unroll
        for (int i = tid; i < NTOK * DIMX / 4; i += BLK) xd[i] = xg[i];
    }
    __syncthreads();

    // ---- Phase 2: QKV GEMM. Order V, K, Q (stage buffer = qs region). ----
    const float scale = 0.1767766952966369f;  // 32^-0.5
    gemm192<0>(tid, R, wqkv + 384, 576, qs, bqkv + 384, 1.0f,  vs);
    gemm192<1>(tid, R, wqkv + 192, 576, qs, bqkv + 192, 1.0f,  kh);
    gemm192<0>(tid, R, wqkv + 0,   576, qs, bqkv + 0,   scale, qs);

    // ---- Phase 3: head-invariant precompute (overwrites x region) ----
    float* Sb = R + R_S;
    float* tb = R + R_TB;
    float* rs = R + R_RS;
    unsigned short* pidx = (unsigned short*)(R + R_PIDX);

    for (int i2 = tid; i2 < TBLROWS * NH; i2 += BLK) {
        int r = i2 / NH, hh = i2 - r * NH;
        tb[i2] = tbl[(r * TOWC + t_idx) * NH + hh];
    }
    for (int e = tid; e < NSQ; e += BLK) {
        int p = (e * 60 + s_sh) % NSQ;
        int n2 = p / NTOK, m2 = p - n2 * NTOK;
        int posv = (n2 / 12 + 6 * (m2 / 12)) * 23 + (n2 % 12) - (m2 % 12) + 11;
        pidx[e] = (unsigned short)(posv * NH);
    }
    __syncthreads();   // covers q epilogue + tb + pidx

    const int wid = tid >> 5, lane = tid & 31;

    // ---- Phase 4: per-head attention ----
    for (int h = 0; h < NH; h++) {
        // S = q_h k_h^T + earth_bias + mask  (6 rows x 3 cols per thread)
        if (tid < 288) {
            const int rg = tid / 24, cg = tid % 24;
            const int r0 = rg * 6;
            const float* qb = qs + r0 * 192 + h * 32;
            const float* kb = kh + h * KH_HEAD + cg * KPITCH;
            u64 acc[6][3];
#pragma unroll
            for (int a = 0; a < 6; a++)
#pragma unroll
                for (int b = 0; b < 3; b++) acc[a][b] = 0ull;
#pragma unroll
            for (int d2 = 0; d2 < 16; d2++) {
                u64 kv0 = *(const u64*)(kb + d2 * 2);
                u64 kv1 = *(const u64*)(kb + 24 * KPITCH + d2 * 2);
                u64 kv2 = *(const u64*)(kb + 48 * KPITCH + d2 * 2);
#pragma unroll
                for (int rr = 0; rr < 6; rr++) {
                    u64 qv = *(const u64*)(qb + rr * 192 + d2 * 2);
                    acc[rr][0] = fma2(qv, kv0, acc[rr][0]);
                    acc[rr][1] = fma2(qv, kv1, acc[rr][1]);
                    acc[rr][2] = fma2(qv, kv2, acc[rr][2]);
                }
            }
#pragma unroll
            for (int rr = 0; rr < 6; rr++) {
#pragma unroll
                for (int m = 0; m < 3; m++) {
                    float2 f = un2(acc[rr][m]);
                    int e = (r0 + rr) * NTOK + cg + m * 24;
                    Sb[e] = f.x + f.y + tb[pidx[e] + h] + maskg[e];
                }
            }
        }
        __syncthreads();

        // softmax: one warp per row (72 = 32 + 32 + 8)
        for (int rr = wid; rr < NTOK; rr += 12) {
            float v0 = Sb[rr * 72 + lane];
            float v1 = Sb[rr * 72 + lane + 32];
            float v2 = (lane < 8) ? Sb[rr * 72 + lane + 64] : -1e30f;
            float m = fmaxf(v0, fmaxf(v1, v2));
#pragma unroll
            for (int o = 16; o > 0; o >>= 1) m = fmaxf(m, __shfl_xor_sync(0xffffffffu, m, o));
            v0 = __expf(v0 - m);
            v1 = __expf(v1 - m);
            v2 = (lane < 8) ? __expf(v2 - m) : 0.0f;
            float sum = v0 + v1 + v2;
#pragma unroll
            for (int o = 16; o > 0; o >>= 1) sum += __shfl_xor_sync(0xffffffffu, sum, o);
            Sb[rr * 72 + lane]      = v0;
            Sb[rr * 72 + lane + 32] = v1;
            if (lane < 8) Sb[rr * 72 + lane + 64] = v2;
            if (lane == 0) rs[rr] = 1.0f / sum;
        }
        __syncthreads();

        // out_h = P @ v_h  (2 rows x 2 u64 per thread) -> overwrite q_h slice
        if (tid < 288) {
            const int rg = tid >> 3, cgg = tid & 7;
            const int i0 = rg * 2;
            const float* vb = vs + h * 32 + cgg * 2;
            const float* s0 = Sb + i0 * 72;
            u64 a00 = 0, a01 = 0, a10 = 0, a11 = 0;
#pragma unroll 8
            for (int j = 0; j < 72; j++) {
                u64 v0 = *(const u64*)(vb + j * 192);
                u64 v1 = *(const u64*)(vb + j * 192 + 16);
                u64 p0 = dup2(s0[j]);
                u64 p1 = dup2(s0[72 + j]);
                a00 = fma2(p0, v0, a00);
                a01 = fma2(p0, v1, a01);
                a10 = fma2(p1, v0, a10);
                a11 = fma2(p1, v1, a11);
            }
            float r0v = rs[i0], r1v = rs[i0 + 1];
            float2 f;
            f = un2(a00); f.x *= r0v; f.y *= r0v;
            *(float2*)(qs + i0 * 192 + h * 32 + cgg * 2) = f;
            f = un2(a01); f.x *= r0v; f.y *= r0v;
            *(float2*)(qs + i0 * 192 + h * 32 + cgg * 2 + 16) = f;
            f = un2(a10); f.x *= r1v; f.y *= r1v;
            *(float2*)(qs + (i0 + 1) * 192 + h * 32 + cgg * 2) = f;
            f = un2(a11); f.x *= r1v; f.y *= r1v;
            *(float2*)(qs + (i0 + 1) * 192 + h * 32 + cgg * 2 + 16) = f;
        }
        __syncthreads();
    }

    // ---- Phase 5: out projection (stage = R region), stream to global ----
    gemm192<2>(tid, qs, wout, 192, R, bout, 1.0f,
               out + (size_t)c * (NTOK * DIMX));
}

extern "C" void kernel_launch(void* const* d_in, const int* in_sizes, int n_in,
                              void* d_out, int out_size)
{
    const float* x    = (const float*)d_in[0];
    const float* mask = (const float*)d_in[1];
    const float* wqkv = (const float*)d_in[2];
    const float* bqkv = (const float*)d_in[3];
    const float* wout = (const float*)d_in[4];
    const float* bout = (const float*)d_in[5];
    const float* tbl  = (const float*)d_in[6];
    float* out = (float*)d_out;

    int B_ = in_sizes[0] / (NTOK * DIMX);   // 1860

    cudaFuncSetAttribute(earth_attn_kernel,
                         cudaFuncAttributeMaxDynamicSharedMemorySize, SMEM_BYTES);
    earth_attn_kernel<<<B_, BLK, SMEM_BYTES>>>(x, mask, wqkv, bqkv, wout, bout, tbl, out);
}

// round 5
// speedup vs baseline: 1.9000x; 1.5685x over previous
#include <cuda_runtime.h>
#include <cuda_bf16.h>

// EarthAttention2D v4: mma.sync (HMMA) bf16 hi/lo projections + SIMT attention.
// One CTA per window. tcgen05 unavailable (harness PTX target lacks 'a' suffix).

typedef unsigned long long u64;
typedef unsigned int u32;

#define NTOK 72
#define DIMX 192
#define NH 6
#define TOWC 31
#define NWC 30
#define BLK 384
#define NSQ 5184
#define TBLROWS 828
#define KPITCH 34
#define KH_HEAD 2448
#define QP 194            // f32 pitch for q / v / attn-out
#define AP 200            // bf16 pitch for X images (conflict-free frag LDS)

// shared float offsets
#define OFF_Q   0         // 72 x QP  (13968)
#define OFF_V   13968     // 72 x QP  (13968)
#define OFF_KH  27936     // 6 x 72 x 34 (14688)
#define OFF_X   42624     // X images: hi 7200 f + lo 7200 f = 14400 f
// attention-phase overlay of OFF_X region:
#define R_S     0
#define R_TB    5184
#define R_RS    10152
#define R_PIDX  10224
#define SMEM_FLOATS 57024
#define SMEM_BYTES (SMEM_FLOATS * 4)   // 228096 <= 232448

// Pre-packed W^T A-fragments (hi/lo), register-exact layout.
// u32 index = ((ct*12 + k)*2 + prec)*128 + lane*4 + r
// ct: 0..35 = QKV cols (Q 0-11, K 12-23, V 24-35), 36..47 = out-proj cols.
__device__ u32 g_wfrag[147456];

// ---------------- helpers ----------------
__device__ __forceinline__ u64 fma2(u64 a, u64 b, u64 c) {
    u64 d;
    asm("fma.rn.f32x2 %0, %1, %2, %3;" : "=l"(d) : "l"(a), "l"(b), "l"(c));
    return d;
}
__device__ __forceinline__ u64 dup2(float x) {
    u64 d; unsigned u = __float_as_uint(x);
    asm("mov.b64 %0, {%1, %1};" : "=l"(d) : "r"(u));
    return d;
}
__device__ __forceinline__ float2 un2(u64 a) {
    float2 f;
    asm("mov.b64 {%0, %1}, %2;" : "=f"(f.x), "=f"(f.y) : "l"(a));
    return f;
}
__device__ __forceinline__ void mma16816(float* d, const u32* a, const u32* b) {
    asm("mma.sync.aligned.m16n8k16.row.col.f32.bf16.bf16.f32 "
        "{%0,%1,%2,%3}, {%4,%5,%6,%7}, {%8,%9}, {%0,%1,%2,%3};"
        : "+f"(d[0]), "+f"(d[1]), "+f"(d[2]), "+f"(d[3])
        : "r"(a[0]), "r"(a[1]), "r"(a[2]), "r"(a[3]), "r"(b[0]), "r"(b[1]));
}
__device__ __forceinline__ u32 packbf(float x0, float x1, u32& lo) {
    __nv_bfloat16 h0 = __float2bfloat16(x0), h1 = __float2bfloat16(x1);
    __nv_bfloat16 l0 = __float2bfloat16(x0 - __bfloat162float(h0));
    __nv_bfloat16 l1 = __float2bfloat16(x1 - __bfloat162float(h1));
    lo = (u32)__bfloat16_as_ushort(l0) | ((u32)__bfloat16_as_ushort(l1) << 16);
    return (u32)__bfloat16_as_ushort(h0) | ((u32)__bfloat16_as_ushort(h1) << 16);
}

// ---------------- pre-kernel: pack W^T fragments ----------------
__global__ void build_wfrags(const float* __restrict__ wqkv,
                             const float* __restrict__ wout) {
    int idx = blockIdx.x * 256 + threadIdx.x;       // 0..147455
    int r    = idx & 3;
    int lane = (idx >> 2) & 31;
    int prec = (idx >> 7) & 1;
    int rest = idx >> 8;                             // ct*12 + k
    int k  = rest % 12;
    int ct = rest / 12;
    int g = lane >> 2, tid2 = lane & 3;
    int i  = g + (r & 1) * 8;                        // output-col within tile
    int kk = tid2 * 2 + (r >> 1) * 8;                // k within tile
    int k_abs = k * 16 + kk;
    const float* W; int stride, n_abs;
    if (ct < 36) { W = wqkv; stride = 576; n_abs = ct * 16 + i; }
    else         { W = wout; stride = 192; n_abs = (ct - 36) * 16 + i; }
    float v0 = W[(size_t)k_abs * stride + n_abs];
    float v1 = W[(size_t)(k_abs + 1) * stride + n_abs];
    u32 lo;
    u32 hi = packbf(v0, v1, lo);
    g_wfrag[idx] = prec ? lo : hi;
}

// ---------------- projection pass (D^T via mma.sync) ----------------
// MODE 0: Q -> qs ((acc+bias)*scale), 1: K -> kh padded, 2: V/OUT -> vs
template<int MODE>
__device__ __forceinline__ void proj_pass(
    int tid, int ct_base,
    const u32* __restrict__ Ah32, const u32* __restrict__ Al32,
    const float* __restrict__ bias, float scale, float* sm)
{
    const int w = tid >> 5, lane = tid & 31;
    const int cg = w & 3, rg = w >> 2;          // colgroup 0..3, rowgroup 0..2
    const int g = lane >> 2, tid2 = lane & 3;

    float acc[3][3][4];
#pragma unroll
    for (int c = 0; c < 3; c++)
#pragma unroll
        for (int rt = 0; rt < 3; rt++)
#pragma unroll
            for (int q = 0; q < 4; q++) acc[c][rt][q] = 0.0f;

    for (int k = 0; k < 12; k++) {
        u32 ah[3][4], al[3][4];
#pragma unroll
        for (int c = 0; c < 3; c++) {
            int ct = ct_base + cg * 3 + c;
            const u32* p = g_wfrag + (size_t)((ct * 12 + k) * 2) * 128 + lane * 4;
            *(uint4*)ah[c] = *(const uint4*)p;
            *(uint4*)al[c] = *(const uint4*)(p + 128);
        }
        u32 bh[3][2], bl[3][2];
#pragma unroll
        for (int rt = 0; rt < 3; rt++) {
            int row = (rg * 3 + rt) * 8 + g;
            int o = row * 100 + k * 8 + tid2;
            bh[rt][0] = Ah32[o]; bh[rt][1] = Ah32[o + 4];
            bl[rt][0] = Al32[o]; bl[rt][1] = Al32[o + 4];
        }
#pragma unroll
        for (int c = 0; c < 3; c++)
#pragma unroll
            for (int rt = 0; rt < 3; rt++) {
                mma16816(acc[c][rt], ah[c], bh[rt]);
                mma16816(acc[c][rt], ah[c], bl[rt]);
                mma16816(acc[c][rt], al[c], bh[rt]);
            }
    }
    // epilogue: d0=(row,col) d1=(row+1,col) d2=(row,col+8) d3=(row+1,col+8)
#pragma unroll
    for (int c = 0; c < 3; c++) {
        int col0 = (cg * 3 + c) * 16 + g;
#pragma unroll
        for (int rt = 0; rt < 3; rt++) {
            int row = (rg * 3 + rt) * 8 + tid2 * 2;
#pragma unroll
            for (int q = 0; q < 4; q++) {
                int rr = row + (q & 1);
                int cc = col0 + (q >> 1) * 8;
                float v = (acc[c][rt][q] + __ldg(bias + cc)) * scale;
                if (MODE == 0)
                    sm[OFF_Q + rr * QP + cc] = v;
                else if (MODE == 1)
                    sm[OFF_KH + (cc >> 5) * KH_HEAD + rr * KPITCH + (cc & 31)] = v;
                else
                    sm[OFF_V + rr * QP + cc] = v;
            }
        }
    }
}

// ---------------- main kernel ----------------
__global__ __launch_bounds__(BLK, 1)
void earth_attn_kernel(
    const float* __restrict__ x,
    const float* __restrict__ mask,
    const float* __restrict__ bqkv,
    const float* __restrict__ bout,
    const float* __restrict__ tbl,
    float* __restrict__ out)
{
    extern __shared__ float sm[];
    const int c   = blockIdx.x;
    const int tid = threadIdx.x;
    const int wid = tid >> 5, lane = tid & 31;

    u32* Ah32 = (u32*)(sm + OFF_X);
    u32* Al32 = Ah32 + 7200;

    const int t_idx = c % TOWC;
    const int s_sh  = c / TOWC;
    const int m_idx = c % NWC;
    const float* maskg = mask + (size_t)m_idx * NSQ;
    const float* xsrc  = x + (size_t)c * (NTOK * DIMX);
    const float qscale = 0.1767766952966369f;  // 32^-0.5

    // ---- stage X as bf16 hi/lo images ----
    for (int i = tid; i < NTOK * 48; i += BLK) {
        int r = i / 48, c4 = i % 48;
        float4 v = ((const float4*)xsrc)[r * 48 + c4];
        int o = r * 100 + c4 * 2;
        u32 lo0, lo1;
        u32 hi0 = packbf(v.x, v.y, lo0);
        u32 hi1 = packbf(v.z, v.w, lo1);
        Ah32[o] = hi0; Ah32[o + 1] = hi1;
        Al32[o] = lo0; Al32[o + 1] = lo1;
    }
    __syncthreads();

    // ---- QKV projections (HMMA) ----
    proj_pass<0>(tid, 0,  Ah32, Al32, bqkv,       qscale, sm);
    proj_pass<1>(tid, 12, Ah32, Al32, bqkv + 192, 1.0f,   sm);
    proj_pass<2>(tid, 24, Ah32, Al32, bqkv + 384, 1.0f,   sm);
    __syncthreads();

    // ---- attention scratch overlays X region ----
    float* qs = sm + OFF_Q;
    float* kh = sm + OFF_KH;
    float* vs = sm + OFF_V;
    float* R  = sm + OFF_X;
    float* Sb = R + R_S;
    float* tb = R + R_TB;
    float* rs = R + R_RS;
    unsigned short* pidx = (unsigned short*)(R + R_PIDX);

    for (int i2 = tid; i2 < TBLROWS * NH; i2 += BLK) {
        int r = i2 / NH, hh = i2 - r * NH;
        tb[i2] = tbl[(r * TOWC + t_idx) * NH + hh];
    }
    for (int e = tid; e < NSQ; e += BLK) {
        int p = (e * 60 + s_sh) % NSQ;
        int n2 = p / NTOK, m2 = p - n2 * NTOK;
        int posv = (n2 / 12 + 6 * (m2 / 12)) * 23 + (n2 % 12) - (m2 % 12) + 11;
        pidx[e] = (unsigned short)(posv * NH);
    }
    __syncthreads();

    // ---- per-head attention (SIMT f32x2) ----
    for (int h = 0; h < NH; h++) {
        if (tid < 288) {
            const int rg = tid / 24, cg = tid % 24;
            const int r0 = rg * 6;
            const float* qb = qs + r0 * QP + h * 32;
            const float* kb = kh + h * KH_HEAD + cg * KPITCH;
            u64 acc[6][3];
#pragma unroll
            for (int a = 0; a < 6; a++)
#pragma unroll
                for (int b = 0; b < 3; b++) acc[a][b] = 0ull;
#pragma unroll
            for (int d2 = 0; d2 < 16; d2++) {
                u64 kv0 = *(const u64*)(kb + d2 * 2);
                u64 kv1 = *(const u64*)(kb + 24 * KPITCH + d2 * 2);
                u64 kv2 = *(const u64*)(kb + 48 * KPITCH + d2 * 2);
#pragma unroll
                for (int rr = 0; rr < 6; rr++) {
                    u64 qv = *(const u64*)(qb + rr * QP + d2 * 2);
                    acc[rr][0] = fma2(qv, kv0, acc[rr][0]);
                    acc[rr][1] = fma2(qv, kv1, acc[rr][1]);
                    acc[rr][2] = fma2(qv, kv2, acc[rr][2]);
                }
            }
#pragma unroll
            for (int rr = 0; rr < 6; rr++) {
#pragma unroll
                for (int m = 0; m < 3; m++) {
                    float2 f = un2(acc[rr][m]);
                    int e = (r0 + rr) * NTOK + cg + m * 24;
                    Sb[e] = f.x + f.y + tb[pidx[e] + h] + maskg[e];
                }
            }
        }
        __syncthreads();

        for (int rr = wid; rr < NTOK; rr += 12) {
            float v0 = Sb[rr * 72 + lane];
            float v1 = Sb[rr * 72 + lane + 32];
            float v2 = (lane < 8) ? Sb[rr * 72 + lane + 64] : -1e30f;
            float m = fmaxf(v0, fmaxf(v1, v2));
#pragma unroll
            for (int o = 16; o > 0; o >>= 1) m = fmaxf(m, __shfl_xor_sync(0xffffffffu, m, o));
            v0 = __expf(v0 - m);
            v1 = __expf(v1 - m);
            v2 = (lane < 8) ? __expf(v2 - m) : 0.0f;
            float sum = v0 + v1 + v2;
#pragma unroll
            for (int o = 16; o > 0; o >>= 1) sum += __shfl_xor_sync(0xffffffffu, sum, o);
            Sb[rr * 72 + lane]      = v0;
            Sb[rr * 72 + lane + 32] = v1;
            if (lane < 8) Sb[rr * 72 + lane + 64] = v2;
            if (lane == 0) rs[rr] = 1.0f / sum;
        }
        __syncthreads();

        if (tid < 288) {
            const int rg = tid >> 3, cgg = tid & 7;
            const int i0 = rg * 2;
            const float* vb = vs + h * 32 + cgg * 2;
            const float* s0 = Sb + i0 * 72;
            u64 a00 = 0, a01 = 0, a10 = 0, a11 = 0;
#pragma unroll 8
            for (int j = 0; j < 72; j++) {
                u64 v0 = *(const u64*)(vb + j * QP);
                u64 v1 = *(const u64*)(vb + j * QP + 16);
                u64 p0 = dup2(s0[j]);
                u64 p1 = dup2(s0[72 + j]);
                a00 = fma2(p0, v0, a00);
                a01 = fma2(p0, v1, a01);
                a10 = fma2(p1, v0, a10);
                a11 = fma2(p1, v1, a11);
            }
            float r0v = rs[i0], r1v = rs[i0 + 1];
            float2 f;
            f = un2(a00); f.x *= r0v; f.y *= r0v;
            *(float2*)(qs + i0 * QP + h * 32 + cgg * 2) = f;
            f = un2(a01); f.x *= r0v; f.y *= r0v;
            *(float2*)(qs + i0 * QP + h * 32 + cgg * 2 + 16) = f;
            f = un2(a10); f.x *= r1v; f.y *= r1v;
            *(float2*)(qs + (i0 + 1) * QP + h * 32 + cgg * 2) = f;
            f = un2(a11); f.x *= r1v; f.y *= r1v;
            *(float2*)(qs + (i0 + 1) * QP + h * 32 + cgg * 2 + 16) = f;
        }
        __syncthreads();
    }

    // ---- out projection: restage attn output (qs) as bf16 images ----
    for (int i = tid; i < NTOK * 48; i += BLK) {
        int r = i / 48, c4 = i % 48;
        const float* p = qs + r * QP + c4 * 4;
        int o = r * 100 + c4 * 2;
        u32 lo0, lo1;
        u32 hi0 = packbf(p[0], p[1], lo0);
        u32 hi1 = packbf(p[2], p[3], lo1);
        Ah32[o] = hi0; Ah32[o + 1] = hi1;
        Al32[o] = lo0; Al32[o + 1] = lo1;
    }
    __syncthreads();
    proj_pass<2>(tid, 36, Ah32, Al32, bout, 1.0f, sm);   // -> vs
    __syncthreads();

    // ---- coalesced store vs -> global ----
    float* og = out + (size_t)c * (NTOK * DIMX);
    for (int i = tid; i < NTOK * DIMX; i += BLK) {
        int r = i / DIMX, cc = i - r * DIMX;
        og[i] = sm[OFF_V + r * QP + cc];
    }
}

extern "C" void kernel_launch(void* const* d_in, const int* in_sizes, int n_in,
                              void* d_out, int out_size)
{
    const float* x    = (const float*)d_in[0];
    const float* mask = (const float*)d_in[1];
    const float* wqkv = (const float*)d_in[2];
    const float* bqkv = (const float*)d_in[3];
    const float* wout = (const float*)d_in[4];
    const float* bout = (const float*)d_in[5];
    const float* tbl  = (const float*)d_in[6];
    float* out = (float*)d_out;

    int B_ = in_sizes[0] / (NTOK * DIMX);   // 1860

    build_wfrags<<<576, 256>>>(wqkv, wout);

    cudaFuncSetAttribute(earth_attn_kernel,
                         cudaFuncAttributeMaxDynamicSharedMemorySize, SMEM_BYTES);
    earth_attn_kernel<<<B_, BLK, SMEM_BYTES>>>(x, mask, bqkv, bout, tbl, out);
}